// round 2
// baseline (speedup 1.0000x reference)
#include <cuda_runtime.h>
#include <math.h>

// Problem constants
#define NB   2
#define CH   128
#define HW   4096      // 64*64
#define NHD  4
#define DH   32
#define CPG  8         // channels per group
#define EPSF 1e-5f
#define ASCALE 0.42044820762685725f   // 32^(-1/4)

typedef unsigned long long ull;

// ---- packed fp32x2 helpers (FFMA2 — Blackwell only, PTX-only path) --------
__device__ __forceinline__ ull ffma2(ull a, ull b, ull c) {
    ull d;
    asm("fma.rn.f32x2 %0, %1, %2, %3;" : "=l"(d) : "l"(a), "l"(b), "l"(c));
    return d;
}
__device__ __forceinline__ ull fmul2(ull a, ull b) {
    ull d;
    asm("mul.rn.f32x2 %0, %1, %2;" : "=l"(d) : "l"(a), "l"(b));
    return d;
}
__device__ __forceinline__ ull pack2(float x) {
    ull d;
    unsigned int u = __float_as_uint(x);
    asm("mov.b64 %0, {%1, %1};" : "=l"(d) : "r"(u));
    return d;
}
__device__ __forceinline__ float psum(ull v) {
    unsigned int lo, hi;
    asm("mov.b64 {%0, %1}, %2;" : "=r"(lo), "=r"(hi) : "l"(v));
    return __uint_as_float(lo) + __uint_as_float(hi);
}

// Scratch (device globals: allocation-free rule)
__device__ __align__(16) float g_xn[NB*CH*HW];   // groupnorm1 output [n][c][p]
__device__ __align__(16) float g_qT[NB*CH*HW];   // q, scaled, [n][h*32+j][p]
__device__ __align__(16) float g_kT[NB*CH*HW];   // k, scaled, [n][h*32+j][p]
__device__ __align__(16) float g_v [NB*CH*HW];   // v, [n*4+h][p][j]
__device__ __align__(16) float g_o [NB*CH*HW];   // attn out, [n][h*32+j][p]
__device__ __align__(16) float g_pj[NB*CH*HW];   // out projection [n][d][p]

// ---------------------------------------------------------------------------
// GroupNorm 1
// ---------------------------------------------------------------------------
__global__ __launch_bounds__(512) void gn1_kernel(const float* __restrict__ x,
                                                  const float* __restrict__ sc,
                                                  const float* __restrict__ off) {
    int b = blockIdx.x;            // 0..31
    int n = b >> 4, g = b & 15;
    const int M = CPG * HW;        // 32768
    size_t base = ((size_t)n * CH + (size_t)g * CPG) * HW;
    const float* xp = x + base;

    float s = 0.f, q = 0.f;
    for (int i = threadIdx.x; i < M; i += 512) {
        float v = xp[i]; s += v; q += v * v;
    }
    __shared__ float ss[512], sq[512];
    ss[threadIdx.x] = s; sq[threadIdx.x] = q;
    __syncthreads();
    for (int st = 256; st > 0; st >>= 1) {
        if (threadIdx.x < st) {
            ss[threadIdx.x] += ss[threadIdx.x + st];
            sq[threadIdx.x] += sq[threadIdx.x + st];
        }
        __syncthreads();
    }
    float mu  = ss[0] / (float)M;
    float var = sq[0] / (float)M - mu * mu;
    float r   = rsqrtf(var + EPSF);

    for (int i = threadIdx.x; i < M; i += 512) {
        int c = g * CPG + (i >> 12);
        g_xn[base + i] = (xp[i] - mu) * r * sc[c] + off[c];
    }
}

// ---------------------------------------------------------------------------
// QKV GEMM with FFMA2: out[n][d][p] = sum_c xn[n][c][p] * w[c][d] + b[d]
// SMEM staged interleaved by c-pairs; accumulators packed over c-parity.
// ---------------------------------------------------------------------------
__global__ __launch_bounds__(256) void qkv_kernel(const float* __restrict__ w,
                                                  const float* __restrict__ bias) {
    int p0 = blockIdx.x * 64, d0 = blockIdx.y * 64, n = blockIdx.z;
    int tid = threadIdx.x, ty = tid >> 4, tx = tid & 15;
    __shared__ float2 Ws[8][64];
    __shared__ float2 Xs[8][64];
    ull acc[4][4];
    #pragma unroll
    for (int i = 0; i < 4; i++)
        #pragma unroll
        for (int j = 0; j < 4; j++) acc[i][j] = 0ull;
    const float* xb = g_xn + (size_t)n * CH * HW;

    int u = tid & 127, lc2 = u >> 4, lq = (u & 15) << 2;
    for (int c0 = 0; c0 < CH; c0 += 16) {
        if (tid < 128) {
            const float* r0 = w + (size_t)(c0 + 2 * lc2) * 384 + d0 + lq;
            float4 a = *(const float4*)r0;
            float4 b = *(const float4*)(r0 + 384);
            *(float4*)&Ws[lc2][lq]     = make_float4(a.x, b.x, a.y, b.y);
            *(float4*)&Ws[lc2][lq + 2] = make_float4(a.z, b.z, a.w, b.w);
        } else {
            const float* r0 = xb + (size_t)(c0 + 2 * lc2) * HW + p0 + lq;
            float4 a = *(const float4*)r0;
            float4 b = *(const float4*)(r0 + HW);
            *(float4*)&Xs[lc2][lq]     = make_float4(a.x, b.x, a.y, b.y);
            *(float4*)&Xs[lc2][lq + 2] = make_float4(a.z, b.z, a.w, b.w);
        }
        __syncthreads();
        #pragma unroll
        for (int c2 = 0; c2 < 8; c2++) {
            ulonglong2 A01 = *(const ulonglong2*)&Ws[c2][ty * 4];
            ulonglong2 A23 = *(const ulonglong2*)&Ws[c2][ty * 4 + 2];
            ull A[4] = {A01.x, A01.y, A23.x, A23.y};
            ull B[4];
            #pragma unroll
            for (int j = 0; j < 4; j++) B[j] = *(const ull*)&Xs[c2][tx + 16 * j];
            #pragma unroll
            for (int i = 0; i < 4; i++)
                #pragma unroll
                for (int j = 0; j < 4; j++)
                    acc[i][j] = ffma2(A[i], B[j], acc[i][j]);
        }
        __syncthreads();
    }
    #pragma unroll
    for (int i = 0; i < 4; i++) {
        int d = d0 + ty * 4 + i;
        float bv = bias[d];
        #pragma unroll
        for (int j = 0; j < 4; j++) {
            int p = p0 + tx + 16 * j;
            float v = psum(acc[i][j]) + bv;
            if (d < 128) {
                g_qT[((size_t)n * CH + d) * HW + p] = v * ASCALE;
            } else if (d < 256) {
                g_kT[((size_t)n * CH + (d - 128)) * HW + p] = v * ASCALE;
            } else {
                int dd = d - 256, h = dd >> 5, jj = dd & 31;
                g_v[(((size_t)n * NHD + h) * HW + p) * DH + jj] = v;
            }
        }
    }
}

// ---------------------------------------------------------------------------
// Flash attention with FFMA2.
// Block = 64 query rows of one (n, head); 256 threads (16x16).
// QK^T packed over d-pairs; PV packed over key-pairs.
// ---------------------------------------------------------------------------
__global__ __launch_bounds__(256, 2) void attn_kernel() {
    int nh = blockIdx.y;                 // 0..7
    int n = nh >> 2, h = nh & 3;
    int q0 = blockIdx.x * 64;
    int tid = threadIdx.x, ty = tid >> 4, tx = tid & 15;

    __shared__ float2 Qs[16][64];        // [d2][row]  (x=even d, y=odd d)
    __shared__ float2 Ks[16][64];        // [d2][key]
    __shared__ float2 Vs[32][32];        // [k2][dim]  (x=even key, y=odd key)
    __shared__ float  Ps[64][68];        // [row][key], padded

    const float* qsrc = g_qT + ((size_t)n * CH + h * DH) * HW;
    const float* ksrc = g_kT + ((size_t)n * CH + h * DH) * HW;
    const float* vsrc = g_v  + (size_t)nh * HW * DH;

    // Load Q tile interleaved by d-pairs: 256 units (16 d2 x 16 row-quads)
    {
        int d2 = tid >> 4, rq = (tid & 15) << 2;
        const float* r0 = qsrc + (size_t)(2 * d2) * HW + q0 + rq;
        float4 a = *(const float4*)r0;
        float4 b = *(const float4*)(r0 + HW);
        *(float4*)&Qs[d2][rq]     = make_float4(a.x, b.x, a.y, b.y);
        *(float4*)&Qs[d2][rq + 2] = make_float4(a.z, b.z, a.w, b.w);
    }

    float m[4], l[4];
    ull O[4][2];
    #pragma unroll
    for (int i = 0; i < 4; i++) { m[i] = -1e30f; l[i] = 0.f; O[i][0] = 0ull; O[i][1] = 0ull; }

    for (int kt = 0; kt < 64; kt++) {
        int k0 = kt * 64;
        __syncthreads();   // prev iteration's QK/PV reads done
        {
            int d2 = tid >> 4, kq = (tid & 15) << 2;
            const float* r0 = ksrc + (size_t)(2 * d2) * HW + k0 + kq;
            float4 a = *(const float4*)r0;
            float4 b = *(const float4*)(r0 + HW);
            *(float4*)&Ks[d2][kq]     = make_float4(a.x, b.x, a.y, b.y);
            *(float4*)&Ks[d2][kq + 2] = make_float4(a.z, b.z, a.w, b.w);
        }
        {
            int k2 = tid >> 3, dq = (tid & 7) << 2;
            const float* r0 = vsrc + (size_t)(k0 + 2 * k2) * DH + dq;
            float4 a = *(const float4*)r0;
            float4 b = *(const float4*)(r0 + DH);
            *(float4*)&Vs[k2][dq]     = make_float4(a.x, b.x, a.y, b.y);
            *(float4*)&Vs[k2][dq + 2] = make_float4(a.z, b.z, a.w, b.w);
        }
        __syncthreads();

        // S = Q K^T tile (64x64), packed over d-pairs; 4 rows x 4 keys/thread
        ull s2[4][4];
        #pragma unroll
        for (int i = 0; i < 4; i++)
            #pragma unroll
            for (int j = 0; j < 4; j++) s2[i][j] = 0ull;
        #pragma unroll
        for (int d2 = 0; d2 < 16; d2++) {
            ulonglong2 A01 = *(const ulonglong2*)&Qs[d2][ty * 4];
            ulonglong2 A23 = *(const ulonglong2*)&Qs[d2][ty * 4 + 2];
            ull A[4] = {A01.x, A01.y, A23.x, A23.y};
            ull B[4];
            #pragma unroll
            for (int j = 0; j < 4; j++) B[j] = *(const ull*)&Ks[d2][tx + 16 * j];
            #pragma unroll
            for (int i = 0; i < 4; i++)
                #pragma unroll
                for (int j = 0; j < 4; j++)
                    s2[i][j] = ffma2(A[i], B[j], s2[i][j]);
        }
        float s[4][4];
        #pragma unroll
        for (int i = 0; i < 4; i++)
            #pragma unroll
            for (int j = 0; j < 4; j++) s[i][j] = psum(s2[i][j]);

        // Online softmax (row reductions across the 16 tx-lanes)
        #pragma unroll
        for (int i = 0; i < 4; i++) {
            float rm = fmaxf(fmaxf(s[i][0], s[i][1]), fmaxf(s[i][2], s[i][3]));
            rm = fmaxf(rm, __shfl_xor_sync(0xffffffffu, rm, 1));
            rm = fmaxf(rm, __shfl_xor_sync(0xffffffffu, rm, 2));
            rm = fmaxf(rm, __shfl_xor_sync(0xffffffffu, rm, 4));
            rm = fmaxf(rm, __shfl_xor_sync(0xffffffffu, rm, 8));
            float mn = fmaxf(m[i], rm);
            float corr = __expf(m[i] - mn);
            float p0v = __expf(s[i][0] - mn);
            float p1v = __expf(s[i][1] - mn);
            float p2v = __expf(s[i][2] - mn);
            float p3v = __expf(s[i][3] - mn);
            float rs = (p0v + p1v) + (p2v + p3v);
            rs += __shfl_xor_sync(0xffffffffu, rs, 1);
            rs += __shfl_xor_sync(0xffffffffu, rs, 2);
            rs += __shfl_xor_sync(0xffffffffu, rs, 4);
            rs += __shfl_xor_sync(0xffffffffu, rs, 8);
            l[i] = l[i] * corr + rs;
            m[i] = mn;
            ull c2 = pack2(corr);
            O[i][0] = fmul2(O[i][0], c2);
            O[i][1] = fmul2(O[i][1], c2);
            int row = ty * 4 + i;
            Ps[row][tx]      = p0v;
            Ps[row][tx + 16] = p1v;
            Ps[row][tx + 32] = p2v;
            Ps[row][tx + 48] = p3v;
        }
        __syncthreads();

        // O += P V, packed over key-pairs; per thread: 4 rows x dims {tx, tx+16}
        #pragma unroll
        for (int k4 = 0; k4 < 16; k4++) {
            ull v0a = *(const ull*)&Vs[2 * k4][tx];
            ull v0b = *(const ull*)&Vs[2 * k4][tx + 16];
            ull v1a = *(const ull*)&Vs[2 * k4 + 1][tx];
            ull v1b = *(const ull*)&Vs[2 * k4 + 1][tx + 16];
            #pragma unroll
            for (int i = 0; i < 4; i++) {
                ulonglong2 Pp = *(const ulonglong2*)&Ps[ty * 4 + i][k4 * 4];
                O[i][0] = ffma2(Pp.x, v0a, O[i][0]);
                O[i][1] = ffma2(Pp.x, v0b, O[i][1]);
                O[i][0] = ffma2(Pp.y, v1a, O[i][0]);
                O[i][1] = ffma2(Pp.y, v1b, O[i][1]);
            }
        }
    }

    // Epilogue: fold packed sums, normalize, write [n][h*32+dim][p]
    #pragma unroll
    for (int i = 0; i < 4; i++) {
        float inv = 1.f / l[i];
        int p = q0 + ty * 4 + i;
        g_o[((size_t)n * CH + h * DH + tx)      * HW + p] = psum(O[i][0]) * inv;
        g_o[((size_t)n * CH + h * DH + tx + 16) * HW + p] = psum(O[i][1]) * inv;
    }
}

// ---------------------------------------------------------------------------
// Out projection with FFMA2: pj[n][d][p] = sum_c o[n][c][p] * w_out[c][d] + b
// ---------------------------------------------------------------------------
__global__ __launch_bounds__(256) void proj_kernel(const float* __restrict__ w,
                                                   const float* __restrict__ bias) {
    int p0 = blockIdx.x * 64, d0 = blockIdx.y * 64, n = blockIdx.z;
    int tid = threadIdx.x, ty = tid >> 4, tx = tid & 15;
    __shared__ float2 Ws[8][64];
    __shared__ float2 Xs[8][64];
    ull acc[4][4];
    #pragma unroll
    for (int i = 0; i < 4; i++)
        #pragma unroll
        for (int j = 0; j < 4; j++) acc[i][j] = 0ull;
    const float* xb = g_o + (size_t)n * CH * HW;

    int u = tid & 127, lc2 = u >> 4, lq = (u & 15) << 2;
    for (int c0 = 0; c0 < CH; c0 += 16) {
        if (tid < 128) {
            const float* r0 = w + (size_t)(c0 + 2 * lc2) * 128 + d0 + lq;
            float4 a = *(const float4*)r0;
            float4 b = *(const float4*)(r0 + 128);
            *(float4*)&Ws[lc2][lq]     = make_float4(a.x, b.x, a.y, b.y);
            *(float4*)&Ws[lc2][lq + 2] = make_float4(a.z, b.z, a.w, b.w);
        } else {
            const float* r0 = xb + (size_t)(c0 + 2 * lc2) * HW + p0 + lq;
            float4 a = *(const float4*)r0;
            float4 b = *(const float4*)(r0 + HW);
            *(float4*)&Xs[lc2][lq]     = make_float4(a.x, b.x, a.y, b.y);
            *(float4*)&Xs[lc2][lq + 2] = make_float4(a.z, b.z, a.w, b.w);
        }
        __syncthreads();
        #pragma unroll
        for (int c2 = 0; c2 < 8; c2++) {
            ulonglong2 A01 = *(const ulonglong2*)&Ws[c2][ty * 4];
            ulonglong2 A23 = *(const ulonglong2*)&Ws[c2][ty * 4 + 2];
            ull A[4] = {A01.x, A01.y, A23.x, A23.y};
            ull B[4];
            #pragma unroll
            for (int j = 0; j < 4; j++) B[j] = *(const ull*)&Xs[c2][tx + 16 * j];
            #pragma unroll
            for (int i = 0; i < 4; i++)
                #pragma unroll
                for (int j = 0; j < 4; j++)
                    acc[i][j] = ffma2(A[i], B[j], acc[i][j]);
        }
        __syncthreads();
    }
    #pragma unroll
    for (int i = 0; i < 4; i++) {
        int d = d0 + ty * 4 + i;
        float bv = bias[d];
        #pragma unroll
        for (int j = 0; j < 4; j++) {
            int p = p0 + tx + 16 * j;
            g_pj[((size_t)n * CH + d) * HW + p] = psum(acc[i][j]) + bv;
        }
    }
}

// ---------------------------------------------------------------------------
// GroupNorm 2 + residual: out = xn + gn2(pj)
// ---------------------------------------------------------------------------
__global__ __launch_bounds__(512) void gn2_kernel(const float* __restrict__ sc,
                                                  const float* __restrict__ off,
                                                  float* __restrict__ out) {
    int b = blockIdx.x;
    int n = b >> 4, g = b & 15;
    const int M = CPG * HW;
    size_t base = ((size_t)n * CH + (size_t)g * CPG) * HW;

    float s = 0.f, q = 0.f;
    for (int i = threadIdx.x; i < M; i += 512) {
        float v = g_pj[base + i]; s += v; q += v * v;
    }
    __shared__ float ss[512], sq[512];
    ss[threadIdx.x] = s; sq[threadIdx.x] = q;
    __syncthreads();
    for (int st = 256; st > 0; st >>= 1) {
        if (threadIdx.x < st) {
            ss[threadIdx.x] += ss[threadIdx.x + st];
            sq[threadIdx.x] += sq[threadIdx.x + st];
        }
        __syncthreads();
    }
    float mu  = ss[0] / (float)M;
    float var = sq[0] / (float)M - mu * mu;
    float r   = rsqrtf(var + EPSF);

    for (int i = threadIdx.x; i < M; i += 512) {
        int c = g * CPG + (i >> 12);
        out[base + i] = g_xn[base + i] + (g_pj[base + i] - mu) * r * sc[c] + off[c];
    }
}

// ---------------------------------------------------------------------------
extern "C" void kernel_launch(void* const* d_in, const int* in_sizes, int n_in,
                              void* d_out, int out_size) {
    const float* x      = (const float*)d_in[0];
    const float* w_qkv  = (const float*)d_in[1];
    const float* b_qkv  = (const float*)d_in[2];
    const float* w_out  = (const float*)d_in[3];
    const float* b_out  = (const float*)d_in[4];
    const float* gn1_s  = (const float*)d_in[5];
    const float* gn1_o  = (const float*)d_in[6];
    const float* gn2_s  = (const float*)d_in[7];
    const float* gn2_o  = (const float*)d_in[8];
    float* out = (float*)d_out;

    gn1_kernel<<<32, 512>>>(x, gn1_s, gn1_o);
    qkv_kernel<<<dim3(HW / 64, 6, NB), 256>>>(w_qkv, b_qkv);
    attn_kernel<<<dim3(HW / 64, NB * NHD), 256>>>();
    proj_kernel<<<dim3(HW / 64, 2, NB), 256>>>(w_out, b_out);
    gn2_kernel<<<32, 512>>>(gn2_s, gn2_o, out);
}